// round 4
// baseline (speedup 1.0000x reference)
#include <cuda_runtime.h>

// Problem constants (fixed by the dataset)
#define BSZ   16384
#define KNUM  1000
#define DIMN  768

#define WARPS_PER_BLOCK 8
#define THREADS (WARPS_PER_BLOCK * 32)

#define V4_PER_LANE 6          // DIM/4/32
#define MASK_V4 (KNUM / 4)     // 250

// Scratch for the per-sample one-hot index (device global: no allocations)
__device__ int g_idx[BSZ];

__device__ __forceinline__ float4 ldcs4(const float4* p) {
    float4 v;
    asm volatile("ld.global.cs.v4.f32 {%0,%1,%2,%3}, [%4];"
                 : "=f"(v.x), "=f"(v.y), "=f"(v.z), "=f"(v.w) : "l"(p));
    return v;
}
__device__ __forceinline__ void stcs4(float4* p, float4 v) {
    asm volatile("st.global.cs.v4.f32 [%0], {%1,%2,%3,%4};"
                 :: "l"(p), "f"(v.x), "f"(v.y), "f"(v.z), "f"(v.w));
}

// ---------------------------------------------------------------------------
// Kernel 1: one-hot index extraction. idx = sum_k mask[k] * k  (exact: mask
// entries are 0.0/1.0 and k < 2^24). Pure streaming, FMA only.
// ---------------------------------------------------------------------------
__global__ __launch_bounds__(THREADS)
void idx_kernel(const float* __restrict__ mask, int* __restrict__ idxbuf)
{
    const int warp = (blockIdx.x * THREADS + threadIdx.x) >> 5;
    const int lane = threadIdx.x & 31;
    if (warp >= BSZ) return;

    const float4* __restrict__ mrow =
        reinterpret_cast<const float4*>(mask + (size_t)warp * KNUM);
    float acc = 0.0f;
    #pragma unroll
    for (int it = 0; it < 8; it++) {
        int i = lane + 32 * it;
        if (i < MASK_V4) {
            float4 v = ldcs4(&mrow[i]);
            float b = (float)(4 * i);
            acc = fmaf(v.x, b,        acc);
            acc = fmaf(v.y, b + 1.0f, acc);
            acc = fmaf(v.z, b + 2.0f, acc);
            acc = fmaf(v.w, b + 3.0f, acc);
        }
    }
    #pragma unroll
    for (int o = 16; o > 0; o >>= 1)
        acc += __shfl_xor_sync(0xffffffffu, acc, o);

    if (lane == 0)
        idxbuf[warp] = __float2int_rn(acc);
}

// ---------------------------------------------------------------------------
// Kernel 2: gather dipole, compute normalized tangent field via scalar algebra
// over six dot products. S rows re-read in pass 2 (L1/L2 hits).
// ---------------------------------------------------------------------------
__global__ __launch_bounds__(THREADS, 4)   // cap at 64 regs -> 4 blocks/SM
void field_kernel(const float* __restrict__ z,      // [BS, DIM]
                  const float* __restrict__ S,      // [K, 2*DIM]
                  const float* __restrict__ A,      // [K, 2]
                  const float* __restrict__ LG,     // [K, 2]
                  const int*   __restrict__ idxbuf, // [BS]
                  float* __restrict__ out)          // [BS, DIM]
{
    const int warp = (blockIdx.x * THREADS + threadIdx.x) >> 5;
    const int lane = threadIdx.x & 31;
    if (warp >= BSZ) return;

    // idx first (tiny, L2) so the S gathers can issue ASAP
    const int idx = __ldg(&idxbuf[warp]);

    // z loads: independent, streamed, retained in registers
    const float4* __restrict__ zrow =
        reinterpret_cast<const float4*>(z + (size_t)warp * DIMN);
    float4 zr[V4_PER_LANE];
    #pragma unroll
    for (int i = 0; i < V4_PER_LANE; i++)
        zr[i] = ldcs4(&zrow[lane + 32 * i]);

    const float a0 = __ldg(&A[2 * idx + 0]);
    const float a1 = __ldg(&A[2 * idx + 1]);
    const float g0 = __expf(__ldg(&LG[2 * idx + 0]));
    const float g1 = __expf(__ldg(&LG[2 * idx + 1]));

    const float4* __restrict__ s0r =
        reinterpret_cast<const float4*>(S + (size_t)idx * (2 * DIMN));
    const float4* __restrict__ s1r = s0r + (DIMN / 4);

    // Pass 1 over S: five dot products (+ zz from registers)
    float zz = 0.0f, ss0 = 0.0f, ss1 = 0.0f;
    float c0 = 0.0f, c1 = 0.0f, s01 = 0.0f;
    #pragma unroll
    for (int i = 0; i < V4_PER_LANE; i++) {
        zz = fmaf(zr[i].x, zr[i].x, zz);
        zz = fmaf(zr[i].y, zr[i].y, zz);
        zz = fmaf(zr[i].z, zr[i].z, zz);
        zz = fmaf(zr[i].w, zr[i].w, zz);
    }
    #pragma unroll 3
    for (int i = 0; i < V4_PER_LANE; i++) {
        const int p = lane + 32 * i;
        float4 s0 = __ldg(&s0r[p]);
        float4 s1 = __ldg(&s1r[p]);
        ss0 = fmaf(s0.x, s0.x, ss0);    ss0 = fmaf(s0.y, s0.y, ss0);
        ss0 = fmaf(s0.z, s0.z, ss0);    ss0 = fmaf(s0.w, s0.w, ss0);
        ss1 = fmaf(s1.x, s1.x, ss1);    ss1 = fmaf(s1.y, s1.y, ss1);
        ss1 = fmaf(s1.z, s1.z, ss1);    ss1 = fmaf(s1.w, s1.w, ss1);
        c0  = fmaf(zr[i].x, s0.x, c0);  c0  = fmaf(zr[i].y, s0.y, c0);
        c0  = fmaf(zr[i].z, s0.z, c0);  c0  = fmaf(zr[i].w, s0.w, c0);
        c1  = fmaf(zr[i].x, s1.x, c1);  c1  = fmaf(zr[i].y, s1.y, c1);
        c1  = fmaf(zr[i].z, s1.z, c1);  c1  = fmaf(zr[i].w, s1.w, c1);
        s01 = fmaf(s0.x, s1.x, s01);    s01 = fmaf(s0.y, s1.y, s01);
        s01 = fmaf(s0.z, s1.z, s01);    s01 = fmaf(s0.w, s1.w, s01);
    }
    #pragma unroll
    for (int o = 16; o > 0; o >>= 1) {
        zz  += __shfl_xor_sync(0xffffffffu, zz,  o);
        ss0 += __shfl_xor_sync(0xffffffffu, ss0, o);
        ss1 += __shfl_xor_sync(0xffffffffu, ss1, o);
        c0  += __shfl_xor_sync(0xffffffffu, c0,  o);
        c1  += __shfl_xor_sync(0xffffffffu, c1,  o);
        s01 += __shfl_xor_sync(0xffffffffu, s01, o);
    }

    // Scalar algebra
    const float sq0 = zz - 2.0f * c0 + ss0;
    const float sq1 = zz - 2.0f * c1 + ss1;
    const float w0  = -2.0f * a0 * g0 * __expf(-g0 * sq0);
    const float w1  = -2.0f * a1 * g1 * __expf(-g1 * sq1);
    const float W   = w0 + w1;
    const float zg  = W * zz - w0 * c0 - w1 * c1;   // z . grad
    const float beta = W - zg;                      // proj = beta z - w0 s0 - w1 s1
    const float nrm2 = beta * beta * zz
                     + w0 * w0 * ss0
                     + w1 * w1 * ss1
                     - 2.0f * beta * w0 * c0
                     - 2.0f * beta * w1 * c1
                     + 2.0f * w0 * w1 * s01;
    const float inv = rsqrtf(nrm2);

    const float bz = beta * inv;
    const float b0 = -w0 * inv;
    const float b1 = -w1 * inv;

    // Pass 2: re-read S (cache hits), combine with retained z, streamed store
    float4* __restrict__ orow =
        reinterpret_cast<float4*>(out + (size_t)warp * DIMN);
    #pragma unroll 3
    for (int i = 0; i < V4_PER_LANE; i++) {
        const int p = lane + 32 * i;
        float4 s0 = __ldg(&s0r[p]);
        float4 s1 = __ldg(&s1r[p]);
        float4 o4;
        o4.x = fmaf(bz, zr[i].x, fmaf(b0, s0.x, b1 * s1.x));
        o4.y = fmaf(bz, zr[i].y, fmaf(b0, s0.y, b1 * s1.y));
        o4.z = fmaf(bz, zr[i].z, fmaf(b0, s0.z, b1 * s1.z));
        o4.w = fmaf(bz, zr[i].w, fmaf(b0, s0.w, b1 * s1.w));
        stcs4(&orow[p], o4);
    }
}

extern "C" void kernel_launch(void* const* d_in, const int* in_sizes, int n_in,
                              void* d_out, int out_size)
{
    const float* mask = (const float*)d_in[0];   // [BS, K]
    const float* z    = (const float*)d_in[1];   // [BS, DIM]
    const float* S    = (const float*)d_in[2];   // [K, 2*DIM]
    const float* A    = (const float*)d_in[3];   // [K, 2]
    const float* LG   = (const float*)d_in[4];   // [K, 2]
    float* out        = (float*)d_out;           // [BS, DIM]

    int* idxbuf;
    cudaGetSymbolAddress((void**)&idxbuf, g_idx);

    const int blocks = BSZ / WARPS_PER_BLOCK;    // 2048
    idx_kernel  <<<blocks, THREADS>>>(mask, idxbuf);
    field_kernel<<<blocks, THREADS>>>(z, S, A, LG, idxbuf, out);
}

// round 5
// speedup vs baseline: 1.1718x; 1.1718x over previous
#include <cuda_runtime.h>

// Problem constants (fixed by the dataset)
#define BSZ   16384
#define KNUM  1000
#define DIMN  768

#define THREADS 256
#define SAMPLES_PER_WARP 2
// 8 warps/block * 2 samples = 16 samples/block
#define BLOCKS (BSZ / (8 * SAMPLES_PER_WARP))   // 1024

#define V4_PER_LANE 6          // DIM/4/32
#define MASK_V4 (KNUM / 4)     // 250

__device__ __forceinline__ float4 ldcs4(const float4* p) {
    float4 v;
    asm volatile("ld.global.cs.v4.f32 {%0,%1,%2,%3}, [%4];"
                 : "=f"(v.x), "=f"(v.y), "=f"(v.z), "=f"(v.w) : "l"(p));
    return v;
}
__device__ __forceinline__ void stcs4(float4* p, float4 v) {
    asm volatile("st.global.cs.v4.f32 [%0], {%1,%2,%3,%4};"
                 :: "l"(p), "f"(v.x), "f"(v.y), "f"(v.z), "f"(v.w));
}

__global__ __launch_bounds__(THREADS, 3)
void css2_kernel(const float* __restrict__ mask,   // [BS, K]
                 const float* __restrict__ z,      // [BS, DIM]
                 const float* __restrict__ S,      // [K, 2*DIM]
                 const float* __restrict__ A,      // [K, 2]
                 const float* __restrict__ LG,     // [K, 2]
                 float* __restrict__ out)          // [BS, DIM]
{
    const int warp = (blockIdx.x * THREADS + threadIdx.x) >> 5;  // 0..8191
    const int lane = threadIdx.x & 31;
    const int sa = 2 * warp;
    const int sb = sa + 1;

    // ---- 1. Interleaved one-hot scans for both samples (16 batched LDG.128)
    //         idx = sum_k mask[k]*k  (exact: entries are 0/1, k < 2^24)
    const float4* __restrict__ ma =
        reinterpret_cast<const float4*>(mask + (size_t)sa * KNUM);
    const float4* __restrict__ mb =
        reinterpret_cast<const float4*>(mask + (size_t)sb * KNUM);
    float accA = 0.0f, accB = 0.0f;
    #pragma unroll
    for (int it = 0; it < 8; it++) {
        int i = lane + 32 * it;
        if (i < MASK_V4) {
            float4 va = ldcs4(&ma[i]);
            float4 vb = ldcs4(&mb[i]);
            float base = (float)(4 * i);
            accA = fmaf(va.x, base,        accA);
            accA = fmaf(va.y, base + 1.0f, accA);
            accA = fmaf(va.z, base + 2.0f, accA);
            accA = fmaf(va.w, base + 3.0f, accA);
            accB = fmaf(vb.x, base,        accB);
            accB = fmaf(vb.y, base + 1.0f, accB);
            accB = fmaf(vb.z, base + 2.0f, accB);
            accB = fmaf(vb.w, base + 3.0f, accB);
        }
    }
    #pragma unroll
    for (int o = 16; o > 0; o >>= 1) {
        accA += __shfl_xor_sync(0xffffffffu, accA, o);
        accB += __shfl_xor_sync(0xffffffffu, accB, o);
    }
    const int ia = __float2int_rn(accA);
    const int ib = __float2int_rn(accB);

    // ---- 2. Per-dipole scalars (float2 loads; L2-resident)
    const float2 Aa  = __ldg(reinterpret_cast<const float2*>(A)  + ia);
    const float2 Ab  = __ldg(reinterpret_cast<const float2*>(A)  + ib);
    const float2 La  = __ldg(reinterpret_cast<const float2*>(LG) + ia);
    const float2 Lb  = __ldg(reinterpret_cast<const float2*>(LG) + ib);
    const float g0a = __expf(La.x), g1a = __expf(La.y);
    const float g0b = __expf(Lb.x), g1b = __expf(Lb.y);

    const float4* __restrict__ za4 =
        reinterpret_cast<const float4*>(z + (size_t)sa * DIMN);
    const float4* __restrict__ zb4 =
        reinterpret_cast<const float4*>(z + (size_t)sb * DIMN);
    const float4* __restrict__ s0a = reinterpret_cast<const float4*>(S + (size_t)ia * (2 * DIMN));
    const float4* __restrict__ s1a = s0a + (DIMN / 4);
    const float4* __restrict__ s0b = reinterpret_cast<const float4*>(S + (size_t)ib * (2 * DIMN));
    const float4* __restrict__ s1b = s0b + (DIMN / 4);

    // ---- 3. Pass 1: six dot products per sample (12 accumulators)
    float zzA = 0.f, ssA0 = 0.f, ssA1 = 0.f, cA0 = 0.f, cA1 = 0.f, sA01 = 0.f;
    float zzB = 0.f, ssB0 = 0.f, ssB1 = 0.f, cB0 = 0.f, cB1 = 0.f, sB01 = 0.f;
    #pragma unroll 3
    for (int i = 0; i < V4_PER_LANE; i++) {
        const int p = lane + 32 * i;
        float4 zv = __ldg(&za4[p]);
        float4 s0 = __ldg(&s0a[p]);
        float4 s1 = __ldg(&s1a[p]);
        zzA  = fmaf(zv.x, zv.x, zzA);   zzA  = fmaf(zv.y, zv.y, zzA);
        zzA  = fmaf(zv.z, zv.z, zzA);   zzA  = fmaf(zv.w, zv.w, zzA);
        ssA0 = fmaf(s0.x, s0.x, ssA0);  ssA0 = fmaf(s0.y, s0.y, ssA0);
        ssA0 = fmaf(s0.z, s0.z, ssA0);  ssA0 = fmaf(s0.w, s0.w, ssA0);
        ssA1 = fmaf(s1.x, s1.x, ssA1);  ssA1 = fmaf(s1.y, s1.y, ssA1);
        ssA1 = fmaf(s1.z, s1.z, ssA1);  ssA1 = fmaf(s1.w, s1.w, ssA1);
        cA0  = fmaf(zv.x, s0.x, cA0);   cA0  = fmaf(zv.y, s0.y, cA0);
        cA0  = fmaf(zv.z, s0.z, cA0);   cA0  = fmaf(zv.w, s0.w, cA0);
        cA1  = fmaf(zv.x, s1.x, cA1);   cA1  = fmaf(zv.y, s1.y, cA1);
        cA1  = fmaf(zv.z, s1.z, cA1);   cA1  = fmaf(zv.w, s1.w, cA1);
        sA01 = fmaf(s0.x, s1.x, sA01);  sA01 = fmaf(s0.y, s1.y, sA01);
        sA01 = fmaf(s0.z, s1.z, sA01);  sA01 = fmaf(s0.w, s1.w, sA01);

        float4 zw = __ldg(&zb4[p]);
        float4 t0 = __ldg(&s0b[p]);
        float4 t1 = __ldg(&s1b[p]);
        zzB  = fmaf(zw.x, zw.x, zzB);   zzB  = fmaf(zw.y, zw.y, zzB);
        zzB  = fmaf(zw.z, zw.z, zzB);   zzB  = fmaf(zw.w, zw.w, zzB);
        ssB0 = fmaf(t0.x, t0.x, ssB0);  ssB0 = fmaf(t0.y, t0.y, ssB0);
        ssB0 = fmaf(t0.z, t0.z, ssB0);  ssB0 = fmaf(t0.w, t0.w, ssB0);
        ssB1 = fmaf(t1.x, t1.x, ssB1);  ssB1 = fmaf(t1.y, t1.y, ssB1);
        ssB1 = fmaf(t1.z, t1.z, ssB1);  ssB1 = fmaf(t1.w, t1.w, ssB1);
        cB0  = fmaf(zw.x, t0.x, cB0);   cB0  = fmaf(zw.y, t0.y, cB0);
        cB0  = fmaf(zw.z, t0.z, cB0);   cB0  = fmaf(zw.w, t0.w, cB0);
        cB1  = fmaf(zw.x, t1.x, cB1);   cB1  = fmaf(zw.y, t1.y, cB1);
        cB1  = fmaf(zw.z, t1.z, cB1);   cB1  = fmaf(zw.w, t1.w, cB1);
        sB01 = fmaf(t0.x, t1.x, sB01);  sB01 = fmaf(t0.y, t1.y, sB01);
        sB01 = fmaf(t0.z, t1.z, sB01);  sB01 = fmaf(t0.w, t1.w, sB01);
    }
    #pragma unroll
    for (int o = 16; o > 0; o >>= 1) {
        zzA  += __shfl_xor_sync(0xffffffffu, zzA,  o);
        ssA0 += __shfl_xor_sync(0xffffffffu, ssA0, o);
        ssA1 += __shfl_xor_sync(0xffffffffu, ssA1, o);
        cA0  += __shfl_xor_sync(0xffffffffu, cA0,  o);
        cA1  += __shfl_xor_sync(0xffffffffu, cA1,  o);
        sA01 += __shfl_xor_sync(0xffffffffu, sA01, o);
        zzB  += __shfl_xor_sync(0xffffffffu, zzB,  o);
        ssB0 += __shfl_xor_sync(0xffffffffu, ssB0, o);
        ssB1 += __shfl_xor_sync(0xffffffffu, ssB1, o);
        cB0  += __shfl_xor_sync(0xffffffffu, cB0,  o);
        cB1  += __shfl_xor_sync(0xffffffffu, cB1,  o);
        sB01 += __shfl_xor_sync(0xffffffffu, sB01, o);
    }

    // ---- 4. Scalar algebra (per sample)
    // sample A
    const float sqA0 = zzA - 2.0f * cA0 + ssA0;
    const float sqA1 = zzA - 2.0f * cA1 + ssA1;
    const float wA0  = -2.0f * Aa.x * g0a * __expf(-g0a * sqA0);
    const float wA1  = -2.0f * Aa.y * g1a * __expf(-g1a * sqA1);
    const float WA   = wA0 + wA1;
    const float zgA  = WA * zzA - wA0 * cA0 - wA1 * cA1;
    const float beA  = WA - zgA;
    const float n2A  = beA * beA * zzA + wA0 * wA0 * ssA0 + wA1 * wA1 * ssA1
                     - 2.0f * beA * wA0 * cA0 - 2.0f * beA * wA1 * cA1
                     + 2.0f * wA0 * wA1 * sA01;
    const float ivA  = rsqrtf(n2A);
    const float bzA  = beA * ivA, b0A = -wA0 * ivA, b1A = -wA1 * ivA;
    // sample B
    const float sqB0 = zzB - 2.0f * cB0 + ssB0;
    const float sqB1 = zzB - 2.0f * cB1 + ssB1;
    const float wB0  = -2.0f * Ab.x * g0b * __expf(-g0b * sqB0);
    const float wB1  = -2.0f * Ab.y * g1b * __expf(-g1b * sqB1);
    const float WB   = wB0 + wB1;
    const float zgB  = WB * zzB - wB0 * cB0 - wB1 * cB1;
    const float beB  = WB - zgB;
    const float n2B  = beB * beB * zzB + wB0 * wB0 * ssB0 + wB1 * wB1 * ssB1
                     - 2.0f * beB * wB0 * cB0 - 2.0f * beB * wB1 * cB1
                     + 2.0f * wB0 * wB1 * sB01;
    const float ivB  = rsqrtf(n2B);
    const float bzB  = beB * ivB, b0B = -wB0 * ivB, b1B = -wB1 * ivB;

    // ---- 5. Pass 2: re-read (L1/L2 hits), combine, streamed store
    float4* __restrict__ oa =
        reinterpret_cast<float4*>(out + (size_t)sa * DIMN);
    float4* __restrict__ ob =
        reinterpret_cast<float4*>(out + (size_t)sb * DIMN);
    #pragma unroll 3
    for (int i = 0; i < V4_PER_LANE; i++) {
        const int p = lane + 32 * i;
        float4 zv = __ldg(&za4[p]);
        float4 s0 = __ldg(&s0a[p]);
        float4 s1 = __ldg(&s1a[p]);
        float4 o4;
        o4.x = fmaf(bzA, zv.x, fmaf(b0A, s0.x, b1A * s1.x));
        o4.y = fmaf(bzA, zv.y, fmaf(b0A, s0.y, b1A * s1.y));
        o4.z = fmaf(bzA, zv.z, fmaf(b0A, s0.z, b1A * s1.z));
        o4.w = fmaf(bzA, zv.w, fmaf(b0A, s0.w, b1A * s1.w));
        stcs4(&oa[p], o4);

        float4 zw = __ldg(&zb4[p]);
        float4 t0 = __ldg(&s0b[p]);
        float4 t1 = __ldg(&s1b[p]);
        float4 o5;
        o5.x = fmaf(bzB, zw.x, fmaf(b0B, t0.x, b1B * t1.x));
        o5.y = fmaf(bzB, zw.y, fmaf(b0B, t0.y, b1B * t1.y));
        o5.z = fmaf(bzB, zw.z, fmaf(b0B, t0.z, b1B * t1.z));
        o5.w = fmaf(bzB, zw.w, fmaf(b0B, t0.w, b1B * t1.w));
        stcs4(&ob[p], o5);
    }
}

extern "C" void kernel_launch(void* const* d_in, const int* in_sizes, int n_in,
                              void* d_out, int out_size)
{
    const float* mask = (const float*)d_in[0];   // [BS, K]
    const float* z    = (const float*)d_in[1];   // [BS, DIM]
    const float* S    = (const float*)d_in[2];   // [K, 2*DIM]
    const float* A    = (const float*)d_in[3];   // [K, 2]
    const float* LG   = (const float*)d_in[4];   // [K, 2]
    float* out        = (float*)d_out;           // [BS, DIM]

    css2_kernel<<<BLOCKS, THREADS>>>(mask, z, S, A, LG, out);
}

// round 6
// speedup vs baseline: 1.2700x; 1.0838x over previous
#include <cuda_runtime.h>

// Problem constants (fixed by the dataset)
#define BSZ   16384
#define KNUM  1000
#define DIMN  768

#define WARPS_PER_BLOCK 8
#define THREADS (WARPS_PER_BLOCK * 32)

#define V4_PER_LANE 6          // DIM/4/32
#define MASK_V4 (KNUM / 4)     // 250

__device__ __forceinline__ float4 ldcs4(const float4* p) {
    float4 v;
    asm volatile("ld.global.cs.v4.f32 {%0,%1,%2,%3}, [%4];"
                 : "=f"(v.x), "=f"(v.y), "=f"(v.z), "=f"(v.w) : "l"(p));
    return v;
}
__device__ __forceinline__ void stcs4(float4* p, float4 v) {
    asm volatile("st.global.cs.v4.f32 [%0], {%1,%2,%3,%4};"
                 :: "l"(p), "f"(v.x), "f"(v.y), "f"(v.z), "f"(v.w));
}

__global__ __launch_bounds__(THREADS)
void css_kernel(const float* __restrict__ mask,   // [BS, K]
                const float* __restrict__ z,      // [BS, DIM]
                const float* __restrict__ S,      // [K, 2*DIM]
                const float* __restrict__ A,      // [K, 2]
                const float* __restrict__ LG,     // [K, 2]
                float* __restrict__ out)          // [BS, DIM]
{
    const int warp = (blockIdx.x * THREADS + threadIdx.x) >> 5;
    const int lane = threadIdx.x & 31;
    if (warp >= BSZ) return;

    // ---- 1. Mask scan: idx = sum_k mask[k]*k (exact; entries 0/1, k < 2^24)
    //         8 batched LDG.128, streamed.
    const float4* __restrict__ mrow =
        reinterpret_cast<const float4*>(mask + (size_t)warp * KNUM);
    float acc = 0.0f;
    #pragma unroll
    for (int it = 0; it < 8; it++) {
        int i = lane + 32 * it;
        if (i < MASK_V4) {
            float4 v = ldcs4(&mrow[i]);
            float b = (float)(4 * i);
            acc = fmaf(v.x, b,        acc);
            acc = fmaf(v.y, b + 1.0f, acc);
            acc = fmaf(v.z, b + 2.0f, acc);
            acc = fmaf(v.w, b + 3.0f, acc);
        }
    }

    // ---- 2. z loads: independent of idx -> issue now, latency hides under
    //         the idx reduction. Retained in registers for the whole kernel.
    const float4* __restrict__ zrow =
        reinterpret_cast<const float4*>(z + (size_t)warp * DIMN);
    float4 zr[V4_PER_LANE];
    #pragma unroll
    for (int i = 0; i < V4_PER_LANE; i++)
        zr[i] = ldcs4(&zrow[lane + 32 * i]);

    #pragma unroll
    for (int o = 16; o > 0; o >>= 1)
        acc += __shfl_xor_sync(0xffffffffu, acc, o);
    const int idx = __float2int_rn(acc);

    // ---- 3. Per-dipole scalars + S row pointers (gather starts here)
    const float2 Av = __ldg(reinterpret_cast<const float2*>(A)  + idx);
    const float2 Lv = __ldg(reinterpret_cast<const float2*>(LG) + idx);
    const float g0 = __expf(Lv.x), g1 = __expf(Lv.y);

    const float4* __restrict__ s0p =
        reinterpret_cast<const float4*>(S + (size_t)idx * (2 * DIMN));
    const float4* __restrict__ s1p = s0p + (DIMN / 4);

    // ---- 4. Load S rows into registers (retained), accumulate all dots.
    //         zz computed first from registers (overlaps S load latency).
    float4 s0r[V4_PER_LANE], s1r[V4_PER_LANE];
    #pragma unroll
    for (int i = 0; i < V4_PER_LANE; i++) {
        const int p = lane + 32 * i;
        s0r[i] = __ldg(&s0p[p]);
        s1r[i] = __ldg(&s1p[p]);
    }

    float zz = 0.0f;
    #pragma unroll
    for (int i = 0; i < V4_PER_LANE; i++) {
        zz = fmaf(zr[i].x, zr[i].x, zz);
        zz = fmaf(zr[i].y, zr[i].y, zz);
        zz = fmaf(zr[i].z, zr[i].z, zz);
        zz = fmaf(zr[i].w, zr[i].w, zz);
    }

    float ss0 = 0.0f, ss1 = 0.0f, c0 = 0.0f, c1 = 0.0f, s01 = 0.0f;
    #pragma unroll
    for (int i = 0; i < V4_PER_LANE; i++) {
        float4 s0 = s0r[i], s1 = s1r[i], zv = zr[i];
        ss0 = fmaf(s0.x, s0.x, ss0);  ss0 = fmaf(s0.y, s0.y, ss0);
        ss0 = fmaf(s0.z, s0.z, ss0);  ss0 = fmaf(s0.w, s0.w, ss0);
        ss1 = fmaf(s1.x, s1.x, ss1);  ss1 = fmaf(s1.y, s1.y, ss1);
        ss1 = fmaf(s1.z, s1.z, ss1);  ss1 = fmaf(s1.w, s1.w, ss1);
        c0  = fmaf(zv.x, s0.x, c0);   c0  = fmaf(zv.y, s0.y, c0);
        c0  = fmaf(zv.z, s0.z, c0);   c0  = fmaf(zv.w, s0.w, c0);
        c1  = fmaf(zv.x, s1.x, c1);   c1  = fmaf(zv.y, s1.y, c1);
        c1  = fmaf(zv.z, s1.z, c1);   c1  = fmaf(zv.w, s1.w, c1);
        s01 = fmaf(s0.x, s1.x, s01);  s01 = fmaf(s0.y, s1.y, s01);
        s01 = fmaf(s0.z, s1.z, s01);  s01 = fmaf(s0.w, s1.w, s01);
    }

    // ---- 5. Single combined reduction (6 independent shuffle chains)
    #pragma unroll
    for (int o = 16; o > 0; o >>= 1) {
        zz  += __shfl_xor_sync(0xffffffffu, zz,  o);
        ss0 += __shfl_xor_sync(0xffffffffu, ss0, o);
        ss1 += __shfl_xor_sync(0xffffffffu, ss1, o);
        c0  += __shfl_xor_sync(0xffffffffu, c0,  o);
        c1  += __shfl_xor_sync(0xffffffffu, c1,  o);
        s01 += __shfl_xor_sync(0xffffffffu, s01, o);
    }

    // ---- 6. Scalar algebra
    const float sq0 = zz - 2.0f * c0 + ss0;
    const float sq1 = zz - 2.0f * c1 + ss1;
    const float w0  = -2.0f * Av.x * g0 * __expf(-g0 * sq0);
    const float w1  = -2.0f * Av.y * g1 * __expf(-g1 * sq1);
    const float W   = w0 + w1;
    const float zg  = W * zz - w0 * c0 - w1 * c1;    // z . grad
    const float beta = W - zg;                       // proj = beta z - w0 s0 - w1 s1
    const float nrm2 = beta * beta * zz
                     + w0 * w0 * ss0
                     + w1 * w1 * ss1
                     - 2.0f * beta * w0 * c0
                     - 2.0f * beta * w1 * c1
                     + 2.0f * w0 * w1 * s01;
    const float inv = rsqrtf(nrm2);
    const float bz = beta * inv;
    const float b0 = -w0 * inv;
    const float b1 = -w1 * inv;

    // ---- 7. Epilogue: pure register -> GMEM streamed stores (no reloads)
    float4* __restrict__ orow =
        reinterpret_cast<float4*>(out + (size_t)warp * DIMN);
    #pragma unroll
    for (int i = 0; i < V4_PER_LANE; i++) {
        float4 o4;
        o4.x = fmaf(bz, zr[i].x, fmaf(b0, s0r[i].x, b1 * s1r[i].x));
        o4.y = fmaf(bz, zr[i].y, fmaf(b0, s0r[i].y, b1 * s1r[i].y));
        o4.z = fmaf(bz, zr[i].z, fmaf(b0, s0r[i].z, b1 * s1r[i].z));
        o4.w = fmaf(bz, zr[i].w, fmaf(b0, s0r[i].w, b1 * s1r[i].w));
        stcs4(&orow[lane + 32 * i], o4);
    }
}

extern "C" void kernel_launch(void* const* d_in, const int* in_sizes, int n_in,
                              void* d_out, int out_size)
{
    const float* mask = (const float*)d_in[0];   // [BS, K]
    const float* z    = (const float*)d_in[1];   // [BS, DIM]
    const float* S    = (const float*)d_in[2];   // [K, 2*DIM]
    const float* A    = (const float*)d_in[3];   // [K, 2]
    const float* LG   = (const float*)d_in[4];   // [K, 2]
    float* out        = (float*)d_out;           // [BS, DIM]

    const int blocks = BSZ / WARPS_PER_BLOCK;    // 2048
    css_kernel<<<blocks, THREADS>>>(mask, z, S, A, LG, out);
}